// round 2
// baseline (speedup 1.0000x reference)
#include <cuda_runtime.h>
#include <cuda_bf16.h>
#include <cstdint>

#define DN 8192
#define DM 8192
#define DD 512
#define DG 10

// ---------------- device scratch (static allocation — allowed) ----------------
__device__ __nv_bfloat16 g_Xb[(size_t)DN * DD];
__device__ __nv_bfloat16 g_Zb[(size_t)DM * DD];
__device__ float g_aa[DN];
__device__ float g_bb[DM];
__device__ float g_c1[DG * DG];
__device__ float g_c2[DG * DG];

// ---------------- helpers (baseline PTX only: sm_80-level, no 'a' features) ----
__device__ __forceinline__ uint32_t smem_u32(const void* p) {
    uint32_t a;
    asm("{ .reg .u64 t; cvta.to.shared.u64 t, %1; cvt.u32.u64 %0, t; }" : "=r"(a) : "l"(p));
    return a;
}

#define CP_ASYNC16(dst, src) \
    asm volatile("cp.async.cg.shared.global [%0], [%1], 16;" :: "r"(dst), "l"(src) : "memory")
#define CP_ASYNC_COMMIT() asm volatile("cp.async.commit_group;" ::: "memory")
#define CP_ASYNC_WAIT(n)  asm volatile("cp.async.wait_group %0;" :: "n"(n) : "memory")

__device__ __forceinline__ void ldsm4(uint32_t r[4], uint32_t addr) {
    asm volatile("ldmatrix.sync.aligned.m8n8.x4.shared.b16 {%0,%1,%2,%3}, [%4];"
                 : "=r"(r[0]), "=r"(r[1]), "=r"(r[2]), "=r"(r[3]) : "r"(addr));
}

__device__ __forceinline__ void mma16816(float c[4], const uint32_t a[4], const uint32_t* b) {
    asm volatile("mma.sync.aligned.m16n8k16.row.col.f32.bf16.bf16.f32 "
                 "{%0,%1,%2,%3}, {%4,%5,%6,%7}, {%8,%9}, {%0,%1,%2,%3};"
                 : "+f"(c[0]), "+f"(c[1]), "+f"(c[2]), "+f"(c[3])
                 : "r"(a[0]), "r"(a[1]), "r"(a[2]), "r"(a[3]), "r"(b[0]), "r"(b[1]));
}

// ---------------- prep: fp32 -> bf16 + row squared-norms ----------------
__global__ void prep_kernel(const float* __restrict__ X, const float* __restrict__ Z) {
    int row = blockIdx.x;
    int which = blockIdx.y;
    const float* src = which ? Z : X;
    __nv_bfloat16* dst = which ? g_Zb : g_Xb;
    float* norms = which ? g_bb : g_aa;
    int t = threadIdx.x;  // 128 threads, 4 floats each
    float4 v = reinterpret_cast<const float4*>(src + (size_t)row * DD)[t];
    __nv_bfloat162 p0 = __floats2bfloat162_rn(v.x, v.y);
    __nv_bfloat162 p1 = __floats2bfloat162_rn(v.z, v.w);
    __nv_bfloat162* d2 = reinterpret_cast<__nv_bfloat162*>(dst + (size_t)row * DD);
    d2[2 * t] = p0;
    d2[2 * t + 1] = p1;
    float s = v.x * v.x + v.y * v.y + v.z * v.z + v.w * v.w;
    #pragma unroll
    for (int o = 16; o; o >>= 1) s += __shfl_xor_sync(0xFFFFFFFFu, s, o);
    __shared__ float ws[4];
    if ((t & 31) == 0) ws[t >> 5] = s;
    __syncthreads();
    if (t == 0) norms[row] = ws[0] + ws[1] + ws[2] + ws[3];
}

// ---------------- group-pair coefficient table ----------------
__global__ void table_kernel(const float* __restrict__ emb, const float* __restrict__ sigma,
                             const float* __restrict__ ls, const float* __restrict__ gdp) {
    int t = threadIdx.x;
    if (t < DG * DG) {
        int a = t / DG, b = t % DG;
        float gd = 0.0f;
        #pragma unroll
        for (int k = 0; k < DG; k++) {
            float d = emb[a * DG + k] - emb[b * DG + k];
            gd += d * d;
        }
        float val = 1.0f / (fabsf(*gdp) * gd + 1.0f);
        float l = *ls;
        float sg = *sigma;
        g_c2[t] = -0.5f * val / (l * l);
        g_c1[t] = sg * sg * powf(val, 0.5f * (float)DD);
    }
}

// ---------------- main GEMM (mma.sync bf16) + fused epilogue ----------------
// CTA tile 128x128, BK=32, 4-stage cp.async pipeline, 8 warps (4 m x 2 n),
// warp tile 32x64 (2 m16 tiles x 8 n8 tiles), 64 fp32 accums/lane.
//
// SMEM: meta region [0, 4096), then 4 stages of (A 128x80B + B 128x80B).
static constexpr int META = 4096;
static constexpr int APITCH = 80;                 // 32 bf16 = 64B, padded to 80B
static constexpr int TILE_BYTES = 128 * APITCH;   // 10240
static constexpr int STAGE_BYTES = 2 * TILE_BYTES;
static constexpr int STAGES = 4;
static constexpr int SMEM_TOTAL = META + STAGES * STAGE_BYTES;  // 86016

__device__ __forceinline__ void load_stage(uint32_t sA, uint32_t sB,
                                           int tm, int tn, int kt, int tid) {
    int r = tid >> 1;            // 0..127
    int cb = (tid & 1) * 2;      // 16B-chunk base: 0 or 2
    const __nv_bfloat16* gA = g_Xb + (size_t)(tm + r) * DD + kt * 32 + cb * 8;
    const __nv_bfloat16* gB = g_Zb + (size_t)(tn + r) * DD + kt * 32 + cb * 8;
    uint32_t dA = sA + r * APITCH + cb * 16;
    uint32_t dB = sB + r * APITCH + cb * 16;
    CP_ASYNC16(dA, gA);
    CP_ASYNC16(dA + 16, gA + 8);
    CP_ASYNC16(dB, gB);
    CP_ASYNC16(dB + 16, gB + 8);
}

__global__ __launch_bounds__(256, 2) void mggp_kernel(const int* __restrict__ gX,
                                                      const int* __restrict__ gZ,
                                                      float* __restrict__ out) {
    extern __shared__ char smem[];
    uint32_t sb = smem_u32(smem);
    int tid = threadIdx.x;
    int wid = tid >> 5, lid = tid & 31;
    int wm = wid & 3, wn = wid >> 2;          // 4 x 2 warp grid
    int tm = blockIdx.y * 128;
    int tn = blockIdx.x * 128;

    int* ga_s = (int*)(smem + 0);
    int* gb_s = (int*)(smem + 512);
    float* aa_s = (float*)(smem + 1024);
    float* bb_s = (float*)(smem + 1536);
    float* c1_s = (float*)(smem + 2048);
    float* c2_s = (float*)(smem + 2448);

    if (tid < 128) {
        ga_s[tid] = gX[tm + tid];
        gb_s[tid] = gZ[tn + tid];
        aa_s[tid] = g_aa[tm + tid];
        bb_s[tid] = g_bb[tn + tid];
    } else if (tid < 228) {
        int k = tid - 128;
        c1_s[k] = g_c1[k];
        c2_s[k] = g_c2[k];
    }

    // prologue: fill 3 stages
    #pragma unroll
    for (int s = 0; s < STAGES - 1; s++) {
        load_stage(sb + META + s * STAGE_BYTES, sb + META + s * STAGE_BYTES + TILE_BYTES,
                   tm, tn, s, tid);
        CP_ASYNC_COMMIT();
    }

    float acc[2][8][4];
    #pragma unroll
    for (int mt = 0; mt < 2; mt++)
        #pragma unroll
        for (int nt = 0; nt < 8; nt++)
            #pragma unroll
            for (int r = 0; r < 4; r++) acc[mt][nt][r] = 0.0f;

    // precompute ldmatrix lane address offsets
    uint32_t a_row = (uint32_t)(wm * 32 + (lid & 15));
    uint32_t a_kof = (uint32_t)((lid >> 4) << 3);
    uint32_t b_row = (uint32_t)(wn * 64 + ((lid >> 4) << 3) + (lid & 7));
    uint32_t b_kof = (uint32_t)(((lid >> 3) & 1) << 3);

    #pragma unroll 1
    for (int kt = 0; kt < 16; kt++) {
        CP_ASYNC_WAIT(2);
        __syncthreads();
        if (kt + STAGES - 1 < 16) {
            int ns = (kt + STAGES - 1) & (STAGES - 1);
            load_stage(sb + META + ns * STAGE_BYTES,
                       sb + META + ns * STAGE_BYTES + TILE_BYTES, tm, tn,
                       kt + STAGES - 1, tid);
        }
        CP_ASYNC_COMMIT();

        int s = kt & (STAGES - 1);
        uint32_t sA = sb + META + s * STAGE_BYTES;
        uint32_t sB = sA + TILE_BYTES;

        #pragma unroll
        for (int kk = 0; kk < 32; kk += 16) {
            uint32_t af[2][4];
            #pragma unroll
            for (int mt = 0; mt < 2; mt++)
                ldsm4(af[mt], sA + (a_row + mt * 16) * APITCH + (kk + a_kof) * 2);
            #pragma unroll
            for (int np = 0; np < 4; np++) {
                uint32_t bf[4];  // two n8 tiles: {b0,b1} x2
                ldsm4(bf, sB + (b_row + np * 16) * APITCH + (kk + b_kof) * 2);
                #pragma unroll
                for (int mt = 0; mt < 2; mt++) {
                    mma16816(acc[mt][2 * np],     af[mt], bf);
                    mma16816(acc[mt][2 * np + 1], af[mt], bf + 2);
                }
            }
        }
    }

    // ---- fused epilogue: dist -> kernel value, direct float2 stores ----
    int r0 = wm * 32 + (lid >> 2);
    int c0 = wn * 64 + (lid & 3) * 2;
    #pragma unroll
    for (int mt = 0; mt < 2; mt++) {
        int rA = r0 + mt * 16;
        int rB = rA + 8;
        float aaA = aa_s[rA], aaB = aa_s[rB];
        int gA = ga_s[rA] * DG, gB = ga_s[rB] * DG;
        #pragma unroll
        for (int nt = 0; nt < 8; nt++) {
            int c = c0 + nt * 8;
            float bb0 = bb_s[c], bb1 = bb_s[c + 1];
            int g0 = gb_s[c], g1 = gb_s[c + 1];

            float d00 = aaA + bb0 - 2.0f * acc[mt][nt][0];
            float d01 = aaA + bb1 - 2.0f * acc[mt][nt][1];
            float d10 = aaB + bb0 - 2.0f * acc[mt][nt][2];
            float d11 = aaB + bb1 - 2.0f * acc[mt][nt][3];

            float2 vA, vB;
            vA.x = c1_s[gA + g0] * __expf(c2_s[gA + g0] * d00);
            vA.y = c1_s[gA + g1] * __expf(c2_s[gA + g1] * d01);
            vB.x = c1_s[gB + g0] * __expf(c2_s[gB + g0] * d10);
            vB.y = c1_s[gB + g1] * __expf(c2_s[gB + g1] * d11);

            *reinterpret_cast<float2*>(out + (size_t)(tm + rA) * DM + tn + c) = vA;
            *reinterpret_cast<float2*>(out + (size_t)(tm + rB) * DM + tn + c) = vB;
        }
    }
}

// ---------------- launch ----------------
extern "C" void kernel_launch(void* const* d_in, const int* in_sizes, int n_in,
                              void* d_out, int out_size) {
    const float* X     = (const float*)d_in[0];
    const float* Z     = (const float*)d_in[1];
    const int*   gX    = (const int*)d_in[2];
    const int*   gZ    = (const int*)d_in[3];
    const float* emb   = (const float*)d_in[4];
    const float* sigma = (const float*)d_in[5];
    const float* ls    = (const float*)d_in[6];
    const float* gdp   = (const float*)d_in[7];
    float* out = (float*)d_out;

    (void)cudaFuncSetAttribute(mggp_kernel, cudaFuncAttributeMaxDynamicSharedMemorySize, SMEM_TOTAL);

    prep_kernel<<<dim3(DN, 2), 128>>>(X, Z);
    table_kernel<<<1, 128>>>(emb, sigma, ls, gdp);
    mggp_kernel<<<dim3(DM / 128, DN / 128), 256, SMEM_TOTAL>>>(gX, gZ, out);
}